// round 2
// baseline (speedup 1.0000x reference)
#include <cuda_runtime.h>
#include <math.h>

#define NB   128   // batch
#define LQ   32    // query tokens
#define LDOC 180   // doc tokens
#define DIM  128   // feature dim
#define NW   8     // nway

typedef unsigned long long u64;

__device__ float g_scores[NB * NW];       // maxsim scores

__device__ __forceinline__ u64 ffma2(u64 a, u64 b, u64 c) {
    u64 d;
    asm("fma.rn.f32x2 %0, %1, %2, %3;" : "=l"(d) : "l"(a), "l"(b), "l"(c));
    return d;
}
__device__ __forceinline__ u64 pack2(float x, float y) {
    u64 r;
    asm("mov.b64 %0, {%1, %2};" : "=l"(r) : "f"(x), "f"(y));
    return r;
}
__device__ __forceinline__ void unpack2(u64 v, float& x, float& y) {
    asm("mov.b64 {%0, %1}, %2;" : "=f"(x), "=f"(y) : "l"(v));
}

// ---------------- kernel B: per-(b,w) MaxSim (query norm folded in) ----------------
// SMEM floats:
//   sdoc  [LDOC][DIM]  swizzled masked doc       23040
//   sqs   [LQ][DIM]    raw -> scaled queries      4096
//   sinv  [DIM]        per-feature inv norm        128
//   smask [192]                                    192
//   sinvq [32]         per-query inv norm           32
#define SM_FLOATS (LDOC * DIM + LQ * DIM + DIM + 192 + 32)
#define SM_BYTES  (SM_FLOATS * 4)

__global__ void __launch_bounds__(128, 2) maxsim_kernel(
    const float* __restrict__ qraw, const float* __restrict__ doc,
    const int* __restrict__ mask)
{
    extern __shared__ float sm[];
    float* sdoc  = sm;
    float* sqs   = sm + LDOC * DIM;
    float* sinv  = sqs + LQ * DIM;
    float* smask = sinv + DIM;
    float* sinvq = smask + 192;

    const int tid = threadIdx.x;
    const int bw  = blockIdx.x;       // b*NW + w
    const int b   = bw >> 3;

    // mask -> smem (as 0/1 float)
    for (int l = tid; l < LDOC; l += 128)
        smask[l] = (mask[bw * LDOC + l] != 0) ? 1.0f : 0.0f;
    __syncthreads();

    // doc slab (masked) into swizzled smem: quad column dq stored at dq ^ (l&31)
    const float4* dg = (const float4*)(doc + (size_t)bw * LDOC * DIM);
    for (int idx = tid; idx < LDOC * (DIM / 4); idx += 128) {
        int l  = idx >> 5;
        int dq = idx & 31;
        float4 v = dg[idx];
        float m = smask[l];
        v.x *= m; v.y *= m; v.z *= m; v.w *= m;
        int dqs = dq ^ (l & 31);
        *(float4*)&sdoc[l * DIM + dqs * 4] = v;
    }

    // raw queries for this batch into sqs
    {
        const float4* qg = (const float4*)(qraw + (size_t)b * LQ * DIM);
        float4* sq4 = (float4*)sqs;
        #pragma unroll
        for (int i = 0; i < LQ * DIM / 4 / 128; i++)
            sq4[tid + i * 128] = qg[tid + i * 128];
    }
    __syncthreads();

    // per-feature inverse norm over tokens (thread = feature d)
    {
        int d  = tid;
        int dq = d >> 2, dr = d & 3;
        float s = 0.f;
        #pragma unroll 4
        for (int l = 0; l < LDOC; l++) {
            float v = sdoc[l * DIM + ((dq ^ (l & 31)) << 2) + dr];
            s += v * v;
        }
        sinv[d] = 1.0f / fmaxf(sqrtf(s), 1e-12f);
    }

    // per-query inverse norm (warp w -> queries w*8..w*8+7)
    {
        const int wq = tid >> 5, lg = tid & 31;
        #pragma unroll
        for (int k = 0; k < 8; k++) {
            int q = wq * 8 + k;
            float v0 = sqs[q * DIM + lg];
            float v1 = sqs[q * DIM + lg + 32];
            float v2 = sqs[q * DIM + lg + 64];
            float v3 = sqs[q * DIM + lg + 96];
            float s = v0 * v0 + v1 * v1 + v2 * v2 + v3 * v3;
            #pragma unroll
            for (int o = 16; o; o >>= 1) s += __shfl_xor_sync(0xffffffffu, s, o);
            if (lg == 0) sinvq[q] = 1.0f / fmaxf(sqrtf(s), 1e-12f);
        }
    }
    __syncthreads();

    // scale queries in place: sqs[q][d] *= invq[q] * invd[d]
    {
        float ivd = sinv[tid];
        #pragma unroll
        for (int q = 0; q < LQ; q++)
            sqs[q * DIM + tid] *= sinvq[q] * ivd;
    }
    __syncthreads();

    // ---- main compute: 8 queries x 6 tokens per thread, packed f32x2 over d ----
    const int qi = tid >> 5;          // warp -> query group (warp-uniform)
    const int lg = tid & 31;          // lane -> token
    const bool v5 = (lg + 160) < LDOC;

    int lrow[6];
    #pragma unroll
    for (int j = 0; j < 6; j++) {
        int l = lg + j * 32;
        if (j == 5 && !v5) l = 0;
        lrow[j] = l;
    }

    u64 acc2[8][6];
    #pragma unroll
    for (int k = 0; k < 8; k++)
        #pragma unroll
        for (int j = 0; j < 6; j++) acc2[k][j] = 0ull;

    const float* qbase = sqs + qi * 8 * DIM;

    for (int dq = 0; dq < 32; dq++) {
        u64 dv0[6], dv1[6];
        #pragma unroll
        for (int j = 0; j < 6; j++) {
            int l = lrow[j];
            float4 t = *(const float4*)&sdoc[l * DIM + ((dq ^ (l & 31)) << 2)];
            dv0[j] = pack2(t.x, t.y);
            dv1[j] = pack2(t.z, t.w);
        }
        #pragma unroll
        for (int k = 0; k < 8; k++) {
            float4 t = *(const float4*)&qbase[k * DIM + dq * 4];
            u64 q0 = pack2(t.x, t.y);
            u64 q1 = pack2(t.z, t.w);
            #pragma unroll
            for (int j = 0; j < 6; j++) {
                acc2[k][j] = ffma2(q0, dv0[j], acc2[k][j]);
                acc2[k][j] = ffma2(q1, dv1[j], acc2[k][j]);
            }
        }
    }

    // reduce: per-thread max over 6 tokens, then cross-lane per query
    __syncthreads();                  // sdoc dead; reuse as smax
    float* smax = sdoc;               // [32 lanes][32 queries]
    #pragma unroll
    for (int k = 0; k < 8; k++) {
        float m = -1e30f;
        #pragma unroll
        for (int j = 0; j < 6; j++) {
            float lo, hi;
            unpack2(acc2[k][j], lo, hi);
            float s = lo + hi;
            if (j < 5 || v5) m = fmaxf(m, s);
        }
        smax[lg * 32 + (qi * 8 + k)] = m;
    }
    __syncthreads();

    if (tid < 32) {
        int q = tid;
        float m = smax[q];
        #pragma unroll
        for (int i = 1; i < 32; i++) m = fmaxf(m, smax[i * 32 + q]);
        #pragma unroll
        for (int o = 16; o; o >>= 1) m += __shfl_xor_sync(0xffffffffu, m, o);
        if (tid == 0) g_scores[bw] = m;
    }
}

// ---------------- kernel C: log_softmax over NW + KL, batchmean ----------------
__global__ void finalize_kernel(const float* __restrict__ labels, float* __restrict__ out) {
    int b = threadIdx.x;              // 128 threads, one batch row each
    float s[NW], lab[NW];
    #pragma unroll
    for (int w = 0; w < NW; w++) {
        s[w]   = g_scores[b * NW + w];
        lab[w] = labels[b * NW + w];
    }
    float m = s[0];
    #pragma unroll
    for (int w = 1; w < NW; w++) m = fmaxf(m, s[w]);
    float se = 0.f;
    #pragma unroll
    for (int w = 0; w < NW; w++) se += expf(s[w] - m);
    float lse = logf(se) + m;
    float acc = 0.f;
    #pragma unroll
    for (int w = 0; w < NW; w++)
        acc += expf(lab[w]) * (lab[w] - (s[w] - lse));
    #pragma unroll
    for (int o = 16; o; o >>= 1) acc += __shfl_xor_sync(0xffffffffu, acc, o);
    __shared__ float red[4];
    if ((b & 31) == 0) red[b >> 5] = acc;
    __syncthreads();
    if (b == 0) out[0] = (red[0] + red[1] + red[2] + red[3]) / (float)NB;
}

// ---------------- launch ----------------
extern "C" void kernel_launch(void* const* d_in, const int* in_sizes, int n_in,
                              void* d_out, int out_size) {
    const float* q      = (const float*)d_in[0];
    const float* doc    = (const float*)d_in[1];
    const int*   mask   = (const int*)d_in[2];
    const float* labels = (const float*)d_in[3];
    float* out = (float*)d_out;

    cudaFuncSetAttribute(maxsim_kernel,
                         cudaFuncAttributeMaxDynamicSharedMemorySize, SM_BYTES);

    maxsim_kernel<<<NB * NW, 128, SM_BYTES>>>(q, doc, mask);
    finalize_kernel<<<1, NB>>>(labels, out);
}

// round 4
// speedup vs baseline: 1.2085x; 1.2085x over previous
#include <cuda_runtime.h>
#include <cuda_bf16.h>
#include <math.h>
#include <stdint.h>

#define NB   128
#define LQ   32
#define LDOC 180
#define DIM  128
#define NW   8

#define AROWS 184            // doc rows padded to 184 (rows 180..183 zero)

// dynamic SMEM byte offsets
#define OFF_MASK  0          // 184 floats
#define OFF_SSQ   768        // 128*4 floats partial sumsq
#define OFF_INVD  2816       // 128 floats
#define OFF_INVQ  3328       // 32 floats
#define OFF_WMAX  3456       // 4*32 floats
#define OFF_DHI   4096       // 184*256 B bf16 doc hi
#define OFF_DLO   (OFF_DHI + 47104)
#define OFF_QHI   (OFF_DLO + 47104)   // 32*256 B
#define OFF_QLO   (OFF_QHI + 8192)
#define SM_BYTES  (OFF_QLO + 8192)    // 114688

__device__ float    g_scores[NB * NW];
__device__ unsigned g_ticket = 0;

__device__ __forceinline__ uint32_t smem_u32(const void* p) {
    uint32_t a;
    asm("{ .reg .u64 t; cvta.to.shared.u64 t, %1; cvt.u32.u64 %0, t; }" : "=r"(a) : "l"(p));
    return a;
}

#define LDSM4(r0, r1, r2, r3, addr) \
    asm volatile("ldmatrix.sync.aligned.m8n8.x4.shared.b16 {%0,%1,%2,%3}, [%4];" \
        : "=r"(r0), "=r"(r1), "=r"(r2), "=r"(r3) : "r"(addr))

__device__ __forceinline__ void mma_bf16(float* c, const uint32_t* a, const uint32_t* b) {
    asm volatile(
        "mma.sync.aligned.m16n8k16.row.col.f32.bf16.bf16.f32 "
        "{%0,%1,%2,%3}, {%4,%5,%6,%7}, {%8,%9}, {%0,%1,%2,%3};"
        : "+f"(c[0]), "+f"(c[1]), "+f"(c[2]), "+f"(c[3])
        : "r"(a[0]), "r"(a[1]), "r"(a[2]), "r"(a[3]), "r"(b[0]), "r"(b[1]));
}

// bf16 hi/lo split of 4 floats -> two packed uint32 pairs (8B hi, 8B lo)
__device__ __forceinline__ void split4(float4 v, uint2& hi, uint2& lo) {
    __nv_bfloat162 h01 = __floats2bfloat162_rn(v.x, v.y);
    __nv_bfloat162 h23 = __floats2bfloat162_rn(v.z, v.w);
    __nv_bfloat162 l01 = __floats2bfloat162_rn(v.x - __bfloat162float(h01.x),
                                               v.y - __bfloat162float(h01.y));
    __nv_bfloat162 l23 = __floats2bfloat162_rn(v.z - __bfloat162float(h23.x),
                                               v.w - __bfloat162float(h23.y));
    hi.x = *(uint32_t*)&h01; hi.y = *(uint32_t*)&h23;
    lo.x = *(uint32_t*)&l01; lo.y = *(uint32_t*)&l23;
}

// swizzled byte offset inside a [rows][256B] bf16 tile: 16B chunk XOR low row bits
__device__ __forceinline__ uint32_t swz(uint32_t row, uint32_t chunk, uint32_t inner) {
    return row * 256u + ((chunk ^ (row & 7u)) << 4) + inner;
}

__global__ void __launch_bounds__(128, 2) maxsim_kernel(
    const float* __restrict__ qraw, const float* __restrict__ doc,
    const int* __restrict__ mask, const float* __restrict__ labels,
    float* __restrict__ out)
{
    extern __shared__ char smc[];
    const uint32_t smb = smem_u32(smc);
    float* smask_f = (float*)(smc + OFF_MASK);
    float* ssq     = (float*)(smc + OFF_SSQ);
    float* sinvd   = (float*)(smc + OFF_INVD);
    float* sinvq   = (float*)(smc + OFF_INVQ);
    float* warpmax = (float*)(smc + OFF_WMAX);

    const int tid  = threadIdx.x;
    const int lane = tid & 31;
    const int w    = tid >> 5;
    const int bw   = blockIdx.x;
    const int b    = bw >> 3;

    // mask -> smem as 0/1 float (pad rows get 0)
    for (int l = tid; l < AROWS; l += 128)
        smask_f[l] = (l < LDOC && mask[bw * LDOC + l] != 0) ? 1.0f : 0.0f;
    __syncthreads();

    // ---- doc stream: global fp32 -> bf16 hi/lo swizzled SMEM + per-feature sumsq ----
    // thread owns quad column dq=lane (features 4dq..4dq+3), rows w, w+4, ...
    {
        const int dq = lane;
        const int d0 = dq * 4;
        const uint32_t chunk = (uint32_t)(d0 >> 3);
        const uint32_t inner = (uint32_t)((d0 & 7) * 2);
        float s0 = 0.f, s1 = 0.f, s2 = 0.f, s3 = 0.f;
        const float4* dg = (const float4*)(doc + (size_t)bw * LDOC * DIM);
        #pragma unroll 5
        for (int i = 0; i < 45; i++) {
            int l = w + 4 * i;
            float4 v = dg[l * 32 + dq];
            float mk = smask_f[l];
            v.x *= mk; v.y *= mk; v.z *= mk; v.w *= mk;
            s0 += v.x * v.x; s1 += v.y * v.y; s2 += v.z * v.z; s3 += v.w * v.w;
            uint2 hv, lv; split4(v, hv, lv);
            uint32_t bo = swz((uint32_t)l, chunk, inner);
            *(uint2*)(smc + OFF_DHI + bo) = hv;
            *(uint2*)(smc + OFF_DLO + bo) = lv;
        }
        { // zero pad row 180+w
            uint32_t bo = swz((uint32_t)(180 + w), chunk, inner);
            *(uint2*)(smc + OFF_DHI + bo) = make_uint2(0u, 0u);
            *(uint2*)(smc + OFF_DLO + bo) = make_uint2(0u, 0u);
        }
        *(float4*)&ssq[tid * 4] = make_float4(s0, s1, s2, s3);
    }

    // ---- per-query inverse norms (warp w -> queries 8w..8w+7) ----
    {
        const float* qb = qraw + (size_t)b * LQ * DIM;
        #pragma unroll
        for (int k = 0; k < 8; k++) {
            int q = w * 8 + k;
            const float* qp = qb + q * DIM + lane;
            float a0 = qp[0], a1 = qp[32], a2 = qp[64], a3 = qp[96];
            float s = a0 * a0 + a1 * a1 + a2 * a2 + a3 * a3;
            #pragma unroll
            for (int o = 16; o; o >>= 1) s += __shfl_xor_sync(0xffffffffu, s, o);
            if (lane == 0) sinvq[q] = 1.0f / fmaxf(sqrtf(s), 1e-12f);
        }
    }
    __syncthreads();

    // ---- per-feature doc inverse norms (thread = feature) ----
    {
        int dqx = tid >> 2, j = tid & 3;
        float s = ssq[dqx * 4 + j] + ssq[(dqx + 32) * 4 + j]
                + ssq[(dqx + 64) * 4 + j] + ssq[(dqx + 96) * 4 + j];
        sinvd[tid] = 1.0f / fmaxf(sqrtf(s), 1e-12f);
    }
    __syncthreads();

    // ---- queries: scale by invq*invd, split to bf16 hi/lo swizzled SMEM ----
    {
        int q = tid >> 2;
        int fbase = (tid & 3) * 32;
        const float* qp = qraw + (size_t)b * LQ * DIM + q * DIM;
        float sq = sinvq[q];
        #pragma unroll
        for (int i = 0; i < 8; i++) {
            int d = fbase + i * 4;
            float4 v = *(const float4*)(qp + d);
            v.x *= sq * sinvd[d];     v.y *= sq * sinvd[d + 1];
            v.z *= sq * sinvd[d + 2]; v.w *= sq * sinvd[d + 3];
            uint2 hv, lv; split4(v, hv, lv);
            uint32_t bo = swz((uint32_t)q, (uint32_t)(d >> 3), (uint32_t)((d & 7) * 2));
            *(uint2*)(smc + OFF_QHI + bo) = hv;
            *(uint2*)(smc + OFF_QLO + bo) = lv;
        }
    }
    __syncthreads();

    // ---- HMMA main loop: warp w covers 3 M-tiles of 16 doc rows ----
    // mrow = w*48 + m*16, except the last tile (176) pulled back to 168.
    int mrow[3];
    #pragma unroll
    for (int m = 0; m < 3; m++) {
        int r = w * 48 + m * 16;
        mrow[m] = (r == 176) ? 168 : r;
    }

    // per-lane ldmatrix row/chunk offsets
    const uint32_t rA = (uint32_t)((lane & 7) + ((lane >> 3) & 1) * 8);
    const uint32_t cA = (uint32_t)(lane >> 4);
    const uint32_t rB = (uint32_t)((lane & 7) + (lane >> 4) * 8);
    const uint32_t cB = (uint32_t)((lane >> 3) & 1);

    const uint32_t dhi = smb + OFF_DHI, dlo = smb + OFF_DLO;
    const uint32_t qhi = smb + OFF_QHI, qlo = smb + OFF_QLO;

    float acc[3][4][4];
    #pragma unroll
    for (int m = 0; m < 3; m++)
        #pragma unroll
        for (int n = 0; n < 4; n++)
            #pragma unroll
            for (int j = 0; j < 4; j++) acc[m][n][j] = 0.f;

    #pragma unroll 2
    for (int k = 0; k < 8; k++) {
        const uint32_t kc = 2u * (uint32_t)k;
        uint32_t bh[8], bl[8];
        // B frags: x4 at q0 covers ntiles 0,1; at q16 covers ntiles 2,3
        {
            uint32_t a0 = qhi + swz(rB, kc + cB, 0);
            uint32_t a1 = qhi + swz(rB + 16u, kc + cB, 0);
            LDSM4(bh[0], bh[1], bh[2], bh[3], a0);
            LDSM4(bh[4], bh[5], bh[6], bh[7], a1);
            uint32_t a2 = qlo + swz(rB, kc + cB, 0);
            uint32_t a3 = qlo + swz(rB + 16u, kc + cB, 0);
            LDSM4(bl[0], bl[1], bl[2], bl[3], a2);
            LDSM4(bl[4], bl[5], bl[6], bl[7], a3);
        }
        #pragma unroll
        for (int m = 0; m < 3; m++) {
            uint32_t r = (uint32_t)mrow[m] + rA;
            uint32_t ah[4], al[4];
            LDSM4(ah[0], ah[1], ah[2], ah[3], dhi + swz(r, kc + cA, 0));
            LDSM4(al[0], al[1], al[2], al[3], dlo + swz(r, kc + cA, 0));
            #pragma unroll
            for (int n = 0; n < 4; n++) {
                mma_bf16(acc[m][n], ah, &bh[n * 2]);
                mma_bf16(acc[m][n], ah, &bl[n * 2]);
                mma_bf16(acc[m][n], al, &bh[n * 2]);
            }
        }
    }

    // ---- reduce: per-column max over this warp's rows, combine, sum ----
    #pragma unroll
    for (int n = 0; n < 4; n++) {
        #pragma unroll
        for (int j = 0; j < 2; j++) {
            float mx = fmaxf(acc[0][n][j], acc[0][n][j + 2]);
            mx = fmaxf(mx, fmaxf(acc[1][n][j], acc[1][n][j + 2]));
            mx = fmaxf(mx, fmaxf(acc[2][n][j], acc[2][n][j + 2]));
            mx = fmaxf(mx, __shfl_xor_sync(0xffffffffu, mx, 4));
            mx = fmaxf(mx, __shfl_xor_sync(0xffffffffu, mx, 8));
            mx = fmaxf(mx, __shfl_xor_sync(0xffffffffu, mx, 16));
            if (lane < 4)
                warpmax[w * 32 + n * 8 + lane * 2 + j] = mx;
        }
    }
    __syncthreads();

    if (tid < 32) {
        float v = warpmax[tid];
        v = fmaxf(v, warpmax[32 + tid]);
        v = fmaxf(v, warpmax[64 + tid]);
        v = fmaxf(v, warpmax[96 + tid]);
        #pragma unroll
        for (int o = 16; o; o >>= 1) v += __shfl_xor_sync(0xffffffffu, v, o);
        if (tid == 0) g_scores[bw] = v;
    }

    // ---- grid ticket: last block computes the KL loss ----
    __shared__ unsigned slast;
    if (tid == 0) {
        __threadfence();
        unsigned t = atomicAdd(&g_ticket, 1u);
        slast = (t == (unsigned)(NB * NW - 1)) ? 1u : 0u;
    }
    __syncthreads();
    if (slast) {
        if (tid == 0) g_ticket = 0;
        __threadfence();
        int bb = tid;                       // 128 threads = 128 batch rows
        float s[NW], lab[NW];
        #pragma unroll
        for (int ww = 0; ww < NW; ww++) {
            s[ww]   = *((volatile float*)&g_scores[bb * NW + ww]);
            lab[ww] = labels[bb * NW + ww];
        }
        float m = s[0];
        #pragma unroll
        for (int ww = 1; ww < NW; ww++) m = fmaxf(m, s[ww]);
        float se = 0.f;
        #pragma unroll
        for (int ww = 0; ww < NW; ww++) se += expf(s[ww] - m);
        float lse = logf(se) + m;
        float accl = 0.f;
        #pragma unroll
        for (int ww = 0; ww < NW; ww++)
            accl += expf(lab[ww]) * (lab[ww] - (s[ww] - lse));
        #pragma unroll
        for (int o = 16; o; o >>= 1) accl += __shfl_xor_sync(0xffffffffu, accl, o);
        __shared__ float red2[4];
        if ((tid & 31) == 0) red2[tid >> 5] = accl;
        __syncthreads();
        if (tid == 0) out[0] = (red2[0] + red2[1] + red2[2] + red2[3]) / (float)NB;
    }
}

// ---------------- launch ----------------
extern "C" void kernel_launch(void* const* d_in, const int* in_sizes, int n_in,
                              void* d_out, int out_size) {
    const float* q      = (const float*)d_in[0];
    const float* doc    = (const float*)d_in[1];
    const int*   mask   = (const int*)d_in[2];
    const float* labels = (const float*)d_in[3];
    float* out = (float*)d_out;

    cudaFuncSetAttribute(maxsim_kernel,
                         cudaFuncAttributeMaxDynamicSharedMemorySize, SM_BYTES);

    maxsim_kernel<<<NB * NW, 128, SM_BYTES>>>(q, doc, mask, labels, out);
}

// round 5
// speedup vs baseline: 1.6140x; 1.3356x over previous
#include <cuda_runtime.h>
#include <cuda_bf16.h>
#include <math.h>
#include <stdint.h>

#define NB   128
#define LQ   32
#define LDOC 180
#define DIM  128
#define NW   8

#define AROWS 184            // doc rows padded (180..183 zero)
#define NTHR  256

// dynamic SMEM byte offsets
#define OFF_SSQ   0                    // 256*4 floats = 4096
#define OFF_INVD  4096                 // 128 floats
#define OFF_INVQ  4608                 // 32 floats
#define OFF_DHI   4736                 // 184*256 B
#define OFF_DLO   (OFF_DHI + 47104)    // 51840
#define OFF_QHI   (OFF_DLO + 47104)    // 98944
#define OFF_QLO   (OFF_QHI + 8192)     // 107136
#define SM_BYTES  (OFF_QLO + 8192)     // 115328  (2 CTAs/SM fit: 2*(115328+1024) < 233472)
#define OFF_WMAX  OFF_QLO              // overlay after post-MMA sync

__device__ float    g_scores[NB * NW];
__device__ unsigned g_ticket = 0;

__device__ __forceinline__ uint32_t smem_u32(const void* p) {
    uint32_t a;
    asm("{ .reg .u64 t; cvta.to.shared.u64 t, %1; cvt.u32.u64 %0, t; }" : "=r"(a) : "l"(p));
    return a;
}

#define LDSM4(r0, r1, r2, r3, addr) \
    asm volatile("ldmatrix.sync.aligned.m8n8.x4.shared.b16 {%0,%1,%2,%3}, [%4];" \
        : "=r"(r0), "=r"(r1), "=r"(r2), "=r"(r3) : "r"(addr))

__device__ __forceinline__ void mma_bf16(float* c, const uint32_t* a, const uint32_t* b) {
    asm volatile(
        "mma.sync.aligned.m16n8k16.row.col.f32.bf16.bf16.f32 "
        "{%0,%1,%2,%3}, {%4,%5,%6,%7}, {%8,%9}, {%0,%1,%2,%3};"
        : "+f"(c[0]), "+f"(c[1]), "+f"(c[2]), "+f"(c[3])
        : "r"(a[0]), "r"(a[1]), "r"(a[2]), "r"(a[3]), "r"(b[0]), "r"(b[1]));
}

// bf16 hi/lo split of 4 floats -> two packed uint32 pairs
__device__ __forceinline__ void split4(float4 v, uint2& hi, uint2& lo) {
    __nv_bfloat162 h01 = __floats2bfloat162_rn(v.x, v.y);
    __nv_bfloat162 h23 = __floats2bfloat162_rn(v.z, v.w);
    __nv_bfloat162 l01 = __floats2bfloat162_rn(v.x - __bfloat162float(h01.x),
                                               v.y - __bfloat162float(h01.y));
    __nv_bfloat162 l23 = __floats2bfloat162_rn(v.z - __bfloat162float(h23.x),
                                               v.w - __bfloat162float(h23.y));
    hi.x = *(uint32_t*)&h01; hi.y = *(uint32_t*)&h23;
    lo.x = *(uint32_t*)&l01; lo.y = *(uint32_t*)&l23;
}

// swizzled byte offset inside a [rows][256B] bf16 tile
__device__ __forceinline__ uint32_t swz(uint32_t row, uint32_t chunk, uint32_t inner) {
    return row * 256u + ((chunk ^ (row & 7u)) << 4) + inner;
}

__global__ void __launch_bounds__(NTHR, 2) maxsim_kernel(
    const float* __restrict__ qraw, const float* __restrict__ doc,
    const int* __restrict__ mask, const float* __restrict__ labels,
    float* __restrict__ out)
{
    extern __shared__ char smc[];
    const uint32_t smb = smem_u32(smc);
    float* ssq   = (float*)(smc + OFF_SSQ);
    float* sinvd = (float*)(smc + OFF_INVD);
    float* sinvq = (float*)(smc + OFF_INVQ);

    const int tid  = threadIdx.x;
    const int lane = tid & 31;
    const int w    = tid >> 5;           // 0..7
    const int bw   = blockIdx.x;
    const int b    = bw >> 3;

    // ---- doc stream: global fp32 -> bf16 hi/lo swizzled SMEM + per-feature sumsq ----
    // thread: quad column dq=lane (features 4dq..4dq+3), rows w+8i, i=0..22
    {
        const int dq = lane;
        const int d0 = dq * 4;
        const uint32_t chunk = (uint32_t)(d0 >> 3);
        const uint32_t inner = (uint32_t)((d0 & 7) * 2);
        float s0 = 0.f, s1 = 0.f, s2 = 0.f, s3 = 0.f;
        const float4* dg = (const float4*)(doc + (size_t)bw * LDOC * DIM);
        const int* mrow = mask + bw * LDOC;

        #pragma unroll 11
        for (int i = 0; i < 22; i++) {
            int l = w + 8 * i;
            float4 v = dg[l * 32 + dq];
            float mk = (mrow[l] != 0) ? 1.0f : 0.0f;   // warp-uniform broadcast
            v.x *= mk; v.y *= mk; v.z *= mk; v.w *= mk;
            s0 += v.x * v.x; s1 += v.y * v.y; s2 += v.z * v.z; s3 += v.w * v.w;
            uint2 hv, lv; split4(v, hv, lv);
            uint32_t bo = swz((uint32_t)l, chunk, inner);
            *(uint2*)(smc + OFF_DHI + bo) = hv;
            *(uint2*)(smc + OFF_DLO + bo) = lv;
        }
        { // tail: row 176+w (valid for w<4), rows 180..183 -> zeros
            int l = w + 176;
            uint2 hv = make_uint2(0u, 0u), lv = make_uint2(0u, 0u);
            if (l < LDOC) {
                float4 v = dg[l * 32 + dq];
                float mk = (mrow[l] != 0) ? 1.0f : 0.0f;
                v.x *= mk; v.y *= mk; v.z *= mk; v.w *= mk;
                s0 += v.x * v.x; s1 += v.y * v.y; s2 += v.z * v.z; s3 += v.w * v.w;
                split4(v, hv, lv);
            }
            uint32_t bo = swz((uint32_t)l, chunk, inner);
            *(uint2*)(smc + OFF_DHI + bo) = hv;
            *(uint2*)(smc + OFF_DLO + bo) = lv;
        }
        *(float4*)&ssq[tid * 4] = make_float4(s0, s1, s2, s3);
    }

    // ---- per-query inverse norms (warp w -> queries 4w..4w+3) ----
    {
        const float* qb = qraw + (size_t)b * LQ * DIM;
        #pragma unroll
        for (int k = 0; k < 4; k++) {
            int q = w * 4 + k;
            const float* qp = qb + q * DIM + lane;
            float a0 = qp[0], a1 = qp[32], a2 = qp[64], a3 = qp[96];
            float s = a0 * a0 + a1 * a1 + a2 * a2 + a3 * a3;
            #pragma unroll
            for (int o = 16; o; o >>= 1) s += __shfl_xor_sync(0xffffffffu, s, o);
            if (lane == 0) sinvq[q] = 1.0f / fmaxf(sqrtf(s), 1e-12f);
        }
    }
    __syncthreads();

    // ---- per-feature doc inverse norms (threads 0..127, feature = tid) ----
    if (tid < DIM) {
        float s = 0.f;
        #pragma unroll
        for (int wp = 0; wp < 8; wp++) s += ssq[wp * 128 + tid];
        sinvd[tid] = 1.0f / fmaxf(sqrtf(s), 1e-12f);
    }
    __syncthreads();

    // ---- queries: scale by invq*invd, split to bf16 hi/lo swizzled SMEM ----
    {
        int q = tid >> 3;                  // 8 threads per query
        int d0 = (tid & 7) * 16;
        const float* qp = qraw + (size_t)b * LQ * DIM + q * DIM;
        float sq = sinvq[q];
        #pragma unroll
        for (int i = 0; i < 4; i++) {
            int d = d0 + i * 4;
            float4 v = *(const float4*)(qp + d);
            v.x *= sq * sinvd[d];     v.y *= sq * sinvd[d + 1];
            v.z *= sq * sinvd[d + 2]; v.w *= sq * sinvd[d + 3];
            uint2 hv, lv; split4(v, hv, lv);
            uint32_t bo = swz((uint32_t)q, (uint32_t)(d >> 3), (uint32_t)((d & 7) * 2));
            *(uint2*)(smc + OFF_QHI + bo) = hv;
            *(uint2*)(smc + OFF_QLO + bo) = lv;
        }
    }
    __syncthreads();

    // ---- HMMA: 12 M-tiles of 16 rows over 8 warps ----
    // warp w: tile0 at w*16; warps 0..3 also tile1 at 128+w*16 (w==3 -> 168)
    const int  mrow0 = w * 16;
    const bool has2  = (w < 4);
    const int  mrow1 = (w < 3) ? 128 + w * 16 : 168;

    const uint32_t rA = (uint32_t)((lane & 7) + ((lane >> 3) & 1) * 8);
    const uint32_t cA = (uint32_t)(lane >> 4);
    const uint32_t rB = (uint32_t)((lane & 7) + (lane >> 4) * 8);
    const uint32_t cB = (uint32_t)((lane >> 3) & 1);

    const uint32_t dhi = smb + OFF_DHI, dlo = smb + OFF_DLO;
    const uint32_t qhi = smb + OFF_QHI, qlo = smb + OFF_QLO;

    float acc[2][4][4];
    #pragma unroll
    for (int m = 0; m < 2; m++)
        #pragma unroll
        for (int n = 0; n < 4; n++)
            #pragma unroll
            for (int j = 0; j < 4; j++) acc[m][n][j] = 0.f;

    #pragma unroll 2
    for (int k = 0; k < 8; k++) {
        const uint32_t kc = 2u * (uint32_t)k;
        uint32_t bh[8], bl[8];
        LDSM4(bh[0], bh[1], bh[2], bh[3], qhi + swz(rB,       kc + cB, 0));
        LDSM4(bh[4], bh[5], bh[6], bh[7], qhi + swz(rB + 16u, kc + cB, 0));
        LDSM4(bl[0], bl[1], bl[2], bl[3], qlo + swz(rB,       kc + cB, 0));
        LDSM4(bl[4], bl[5], bl[6], bl[7], qlo + swz(rB + 16u, kc + cB, 0));

        {
            uint32_t r = (uint32_t)mrow0 + rA;
            uint32_t ah[4], al[4];
            LDSM4(ah[0], ah[1], ah[2], ah[3], dhi + swz(r, kc + cA, 0));
            LDSM4(al[0], al[1], al[2], al[3], dlo + swz(r, kc + cA, 0));
            #pragma unroll
            for (int n = 0; n < 4; n++) {
                mma_bf16(acc[0][n], ah, &bh[n * 2]);
                mma_bf16(acc[0][n], ah, &bl[n * 2]);
                mma_bf16(acc[0][n], al, &bh[n * 2]);
            }
        }
        if (has2) {
            uint32_t r = (uint32_t)mrow1 + rA;
            uint32_t ah[4], al[4];
            LDSM4(ah[0], ah[1], ah[2], ah[3], dhi + swz(r, kc + cA, 0));
            LDSM4(al[0], al[1], al[2], al[3], dlo + swz(r, kc + cA, 0));
            #pragma unroll
            for (int n = 0; n < 4; n++) {
                mma_bf16(acc[1][n], ah, &bh[n * 2]);
                mma_bf16(acc[1][n], ah, &bl[n * 2]);
                mma_bf16(acc[1][n], al, &bh[n * 2]);
            }
        }
    }
    __syncthreads();                       // Q tiles dead; warpmax overlays qlo

    float* warpmax = (float*)(smc + OFF_WMAX);
    #pragma unroll
    for (int n = 0; n < 4; n++) {
        #pragma unroll
        for (int j = 0; j < 2; j++) {
            float mx = fmaxf(acc[0][n][j], acc[0][n][j + 2]);
            if (has2) mx = fmaxf(mx, fmaxf(acc[1][n][j], acc[1][n][j + 2]));
            mx = fmaxf(mx, __shfl_xor_sync(0xffffffffu, mx, 4));
            mx = fmaxf(mx, __shfl_xor_sync(0xffffffffu, mx, 8));
            mx = fmaxf(mx, __shfl_xor_sync(0xffffffffu, mx, 16));
            if (lane < 4)
                warpmax[w * 32 + n * 8 + lane * 2 + j] = mx;
        }
    }
    __syncthreads();

    if (tid < 32) {
        float v = warpmax[tid];
        #pragma unroll
        for (int wp = 1; wp < 8; wp++) v = fmaxf(v, warpmax[wp * 32 + tid]);
        #pragma unroll
        for (int o = 16; o; o >>= 1) v += __shfl_xor_sync(0xffffffffu, v, o);
        if (tid == 0) g_scores[bw] = v;
    }

    // ---- grid ticket: last block computes the KL loss ----
    __shared__ unsigned slast;
    if (tid == 0) {
        __threadfence();
        unsigned t = atomicAdd(&g_ticket, 1u);
        slast = (t == (unsigned)(NB * NW - 1)) ? 1u : 0u;
    }
    __syncthreads();
    if (slast) {
        if (tid == 0) g_ticket = 0;
        __threadfence();
        float accl = 0.f;
        if (tid < NB) {
            float s[NW], lab[NW];
            #pragma unroll
            for (int ww = 0; ww < NW; ww++) {
                s[ww]   = *((volatile float*)&g_scores[tid * NW + ww]);
                lab[ww] = labels[tid * NW + ww];
            }
            float m = s[0];
            #pragma unroll
            for (int ww = 1; ww < NW; ww++) m = fmaxf(m, s[ww]);
            float se = 0.f;
            #pragma unroll
            for (int ww = 0; ww < NW; ww++) se += expf(s[ww] - m);
            float lse = logf(se) + m;
            #pragma unroll
            for (int ww = 0; ww < NW; ww++)
                accl += expf(lab[ww]) * (lab[ww] - (s[ww] - lse));
        }
        #pragma unroll
        for (int o = 16; o; o >>= 1) accl += __shfl_xor_sync(0xffffffffu, accl, o);
        __shared__ float red2[8];
        if (lane == 0) red2[w] = accl;
        __syncthreads();
        if (tid == 0) {
            float t2 = 0.f;
            #pragma unroll
            for (int i = 0; i < 8; i++) t2 += red2[i];
            out[0] = t2 / (float)NB;
        }
    }
}

// ---------------- launch ----------------
extern "C" void kernel_launch(void* const* d_in, const int* in_sizes, int n_in,
                              void* d_out, int out_size) {
    const float* q      = (const float*)d_in[0];
    const float* doc    = (const float*)d_in[1];
    const int*   mask   = (const int*)d_in[2];
    const float* labels = (const float*)d_in[3];
    float* out = (float*)d_out;

    cudaFuncSetAttribute(maxsim_kernel,
                         cudaFuncAttributeMaxDynamicSharedMemorySize, SM_BYTES);

    maxsim_kernel<<<NB * NW, NTHR, SM_BYTES>>>(q, doc, mask, labels, out);
}

// round 6
// speedup vs baseline: 2.0566x; 1.2742x over previous
#include <cuda_runtime.h>
#include <cuda_fp16.h>
#include <math.h>
#include <stdint.h>

#define NB   128
#define LQ   32
#define LDOC 180
#define DIM  128
#define NW   8

#define AROWS 184            // doc rows padded (180..183 zero)
#define NTHR  256
#define QSCALE    64.0f
#define QSCALE_IV (1.0f / 64.0f)

// dynamic SMEM byte offsets
#define OFF_SSQ   0                    // 256*4 floats = 4096
#define OFF_INVD  4096                 // 128 floats
#define OFF_INVQ  4608                 // 32 floats
#define OFF_D     4736                 // 184*256 B fp16 doc
#define OFF_QHI   (OFF_D + 47104)      // 51840, 32*256 B
#define OFF_QLO   (OFF_QHI + 8192)     // 60032
#define SM_BYTES  (OFF_QLO + 8192)     // 68224 -> 3 CTAs/SM
#define OFF_WMAX  OFF_QLO              // overlay after post-MMA sync

__device__ float    g_scores[NB * NW];
__device__ unsigned g_ticket = 0;

__device__ __forceinline__ uint32_t smem_u32(const void* p) {
    uint32_t a;
    asm("{ .reg .u64 t; cvta.to.shared.u64 t, %1; cvt.u32.u64 %0, t; }" : "=r"(a) : "l"(p));
    return a;
}

#define LDSM4(r0, r1, r2, r3, addr) \
    asm volatile("ldmatrix.sync.aligned.m8n8.x4.shared.b16 {%0,%1,%2,%3}, [%4];" \
        : "=r"(r0), "=r"(r1), "=r"(r2), "=r"(r3) : "r"(addr))

__device__ __forceinline__ void mma_f16(float* c, const uint32_t* a, const uint32_t* b) {
    asm volatile(
        "mma.sync.aligned.m16n8k16.row.col.f32.f16.f16.f32 "
        "{%0,%1,%2,%3}, {%4,%5,%6,%7}, {%8,%9}, {%0,%1,%2,%3};"
        : "+f"(c[0]), "+f"(c[1]), "+f"(c[2]), "+f"(c[3])
        : "r"(a[0]), "r"(a[1]), "r"(a[2]), "r"(a[3]), "r"(b[0]), "r"(b[1]));
}

// 4 floats -> packed fp16 (hi only)
__device__ __forceinline__ uint2 h4(float4 v) {
    __half2 a = __floats2half2_rn(v.x, v.y);
    __half2 b = __floats2half2_rn(v.z, v.w);
    uint2 r;
    r.x = *(uint32_t*)&a; r.y = *(uint32_t*)&b;
    return r;
}
// 4 floats -> fp16 hi + fp16 lo (residual)
__device__ __forceinline__ void h4split(float4 v, uint2& hi, uint2& lo) {
    __half2 a = __floats2half2_rn(v.x, v.y);
    __half2 b = __floats2half2_rn(v.z, v.w);
    __half2 la = __floats2half2_rn(v.x - __half2float(a.x), v.y - __half2float(a.y));
    __half2 lb = __floats2half2_rn(v.z - __half2float(b.x), v.w - __half2float(b.y));
    hi.x = *(uint32_t*)&a;  hi.y = *(uint32_t*)&b;
    lo.x = *(uint32_t*)&la; lo.y = *(uint32_t*)&lb;
}

// swizzled byte offset inside a [rows][256B] fp16 tile
__device__ __forceinline__ uint32_t swz(uint32_t row, uint32_t chunk, uint32_t inner) {
    return row * 256u + ((chunk ^ (row & 7u)) << 4) + inner;
}

__global__ void __launch_bounds__(NTHR, 3) maxsim_kernel(
    const float* __restrict__ qraw, const float* __restrict__ doc,
    const int* __restrict__ mask, const float* __restrict__ labels,
    float* __restrict__ out)
{
    extern __shared__ char smc[];
    const uint32_t smb = smem_u32(smc);
    float* ssq   = (float*)(smc + OFF_SSQ);
    float* sinvd = (float*)(smc + OFF_INVD);
    float* sinvq = (float*)(smc + OFF_INVQ);

    const int tid  = threadIdx.x;
    const int lane = tid & 31;
    const int w    = tid >> 5;           // 0..7
    const int bw   = blockIdx.x;
    const int b    = bw >> 3;

    // ---- doc stream: global fp32 -> fp16 swizzled SMEM + per-feature sumsq ----
    {
        const int dq = lane;
        const int d0 = dq * 4;
        const uint32_t chunk = (uint32_t)(d0 >> 3);
        const uint32_t inner = (uint32_t)((d0 & 7) * 2);
        float s0 = 0.f, s1 = 0.f, s2 = 0.f, s3 = 0.f;
        const float4* dg = (const float4*)(doc + (size_t)bw * LDOC * DIM);
        const int* mrow = mask + bw * LDOC;

        #pragma unroll 11
        for (int i = 0; i < 22; i++) {
            int l = w + 8 * i;
            float4 v = dg[l * 32 + dq];
            float mk = (mrow[l] != 0) ? 1.0f : 0.0f;
            v.x *= mk; v.y *= mk; v.z *= mk; v.w *= mk;
            s0 += v.x * v.x; s1 += v.y * v.y; s2 += v.z * v.z; s3 += v.w * v.w;
            *(uint2*)(smc + OFF_D + swz((uint32_t)l, chunk, inner)) = h4(v);
        }
        { // tail: row 176+w (valid for w<4), rows 180..183 -> zeros
            int l = w + 176;
            uint2 hv = make_uint2(0u, 0u);
            if (l < LDOC) {
                float4 v = dg[l * 32 + dq];
                float mk = (mrow[l] != 0) ? 1.0f : 0.0f;
                v.x *= mk; v.y *= mk; v.z *= mk; v.w *= mk;
                s0 += v.x * v.x; s1 += v.y * v.y; s2 += v.z * v.z; s3 += v.w * v.w;
                hv = h4(v);
            }
            *(uint2*)(smc + OFF_D + swz((uint32_t)l, chunk, inner)) = hv;
        }
        *(float4*)&ssq[tid * 4] = make_float4(s0, s1, s2, s3);
    }

    // ---- per-query inverse norms (warp w -> queries 4w..4w+3) ----
    {
        const float* qb = qraw + (size_t)b * LQ * DIM;
        #pragma unroll
        for (int k = 0; k < 4; k++) {
            int q = w * 4 + k;
            const float* qp = qb + q * DIM + lane;
            float a0 = qp[0], a1 = qp[32], a2 = qp[64], a3 = qp[96];
            float s = a0 * a0 + a1 * a1 + a2 * a2 + a3 * a3;
            #pragma unroll
            for (int o = 16; o; o >>= 1) s += __shfl_xor_sync(0xffffffffu, s, o);
            if (lane == 0) sinvq[q] = 1.0f / fmaxf(sqrtf(s), 1e-12f);
        }
    }
    __syncthreads();

    // ---- per-feature doc inverse norms ----
    if (tid < DIM) {
        float s = 0.f;
        #pragma unroll
        for (int wp = 0; wp < 8; wp++) s += ssq[wp * 128 + tid];
        sinvd[tid] = 1.0f / fmaxf(sqrtf(s), 1e-12f);
    }
    __syncthreads();

    // ---- queries: scale by invq*invd*QSCALE, fp16 hi/lo to SMEM ----
    {
        int q = tid >> 3;                  // 8 threads per query
        int d0 = (tid & 7) * 16;
        const float* qp = qraw + (size_t)b * LQ * DIM + q * DIM;
        float sq = sinvq[q] * QSCALE;
        #pragma unroll
        for (int i = 0; i < 4; i++) {
            int d = d0 + i * 4;
            float4 v = *(const float4*)(qp + d);
            v.x *= sq * sinvd[d];     v.y *= sq * sinvd[d + 1];
            v.z *= sq * sinvd[d + 2]; v.w *= sq * sinvd[d + 3];
            uint2 hv, lv; h4split(v, hv, lv);
            uint32_t bo = swz((uint32_t)q, (uint32_t)(d >> 3), (uint32_t)((d & 7) * 2));
            *(uint2*)(smc + OFF_QHI + bo) = hv;
            *(uint2*)(smc + OFF_QLO + bo) = lv;
        }
    }
    __syncthreads();

    // ---- HMMA: 12 M-tiles of 16 rows over 8 warps, 2 precision terms ----
    const int  mrow0 = w * 16;
    const bool has2  = (w < 4);
    const int  mrow1 = (w < 3) ? 128 + w * 16 : 168;

    const uint32_t rA = (uint32_t)((lane & 7) + ((lane >> 3) & 1) * 8);
    const uint32_t cA = (uint32_t)(lane >> 4);
    const uint32_t rB = (uint32_t)((lane & 7) + (lane >> 4) * 8);
    const uint32_t cB = (uint32_t)((lane >> 3) & 1);

    const uint32_t dti = smb + OFF_D;
    const uint32_t qhi = smb + OFF_QHI, qlo = smb + OFF_QLO;

    float acc[2][4][4];
    #pragma unroll
    for (int m = 0; m < 2; m++)
        #pragma unroll
        for (int n = 0; n < 4; n++)
            #pragma unroll
            for (int j = 0; j < 4; j++) acc[m][n][j] = 0.f;

    #pragma unroll 2
    for (int k = 0; k < 8; k++) {
        const uint32_t kc = 2u * (uint32_t)k;
        uint32_t bh[8], bl[8];
        LDSM4(bh[0], bh[1], bh[2], bh[3], qhi + swz(rB,       kc + cB, 0));
        LDSM4(bh[4], bh[5], bh[6], bh[7], qhi + swz(rB + 16u, kc + cB, 0));
        LDSM4(bl[0], bl[1], bl[2], bl[3], qlo + swz(rB,       kc + cB, 0));
        LDSM4(bl[4], bl[5], bl[6], bl[7], qlo + swz(rB + 16u, kc + cB, 0));

        {
            uint32_t ah[4];
            LDSM4(ah[0], ah[1], ah[2], ah[3], dti + swz((uint32_t)mrow0 + rA, kc + cA, 0));
            #pragma unroll
            for (int n = 0; n < 4; n++) {
                mma_f16(acc[0][n], ah, &bh[n * 2]);
                mma_f16(acc[0][n], ah, &bl[n * 2]);
            }
        }
        if (has2) {
            uint32_t ah[4];
            LDSM4(ah[0], ah[1], ah[2], ah[3], dti + swz((uint32_t)mrow1 + rA, kc + cA, 0));
            #pragma unroll
            for (int n = 0; n < 4; n++) {
                mma_f16(acc[1][n], ah, &bh[n * 2]);
                mma_f16(acc[1][n], ah, &bl[n * 2]);
            }
        }
    }
    __syncthreads();                       // Q-lo dead; warpmax overlays it

    float* warpmax = (float*)(smc + OFF_WMAX);
    #pragma unroll
    for (int n = 0; n < 4; n++) {
        #pragma unroll
        for (int j = 0; j < 2; j++) {
            float mx = fmaxf(acc[0][n][j], acc[0][n][j + 2]);
            if (has2) mx = fmaxf(mx, fmaxf(acc[1][n][j], acc[1][n][j + 2]));
            mx = fmaxf(mx, __shfl_xor_sync(0xffffffffu, mx, 4));
            mx = fmaxf(mx, __shfl_xor_sync(0xffffffffu, mx, 8));
            mx = fmaxf(mx, __shfl_xor_sync(0xffffffffu, mx, 16));
            if (lane < 4)
                warpmax[w * 32 + n * 8 + lane * 2 + j] = mx * QSCALE_IV;
        }
    }
    __syncthreads();

    if (tid < 32) {
        float v = warpmax[tid];
        #pragma unroll
        for (int wp = 1; wp < 8; wp++) v = fmaxf(v, warpmax[wp * 32 + tid]);
        #pragma unroll
        for (int o = 16; o; o >>= 1) v += __shfl_xor_sync(0xffffffffu, v, o);
        if (tid == 0) g_scores[bw] = v;
    }

    // ---- grid ticket: last block computes the KL loss ----
    __shared__ unsigned slast;
    if (tid == 0) {
        __threadfence();
        unsigned t = atomicAdd(&g_ticket, 1u);
        slast = (t == (unsigned)(NB * NW - 1)) ? 1u : 0u;
    }
    __syncthreads();
    if (slast) {
        if (tid == 0) g_ticket = 0;
        __threadfence();
        float accl = 0.f;
        if (tid < NB) {
            float s[NW], lab[NW];
            #pragma unroll
            for (int ww = 0; ww < NW; ww++) {
                s[ww]   = *((volatile float*)&g_scores[tid * NW + ww]);
                lab[ww] = labels[tid * NW + ww];
            }
            float m = s[0];
            #pragma unroll
            for (int ww = 1; ww < NW; ww++) m = fmaxf(m, s[ww]);
            float se = 0.f;
            #pragma unroll
            for (int ww = 0; ww < NW; ww++) se += expf(s[ww] - m);
            float lse = logf(se) + m;
            #pragma unroll
            for (int ww = 0; ww < NW; ww++)
                accl += expf(lab[ww]) * (lab[ww] - (s[ww] - lse));
        }
        #pragma unroll
        for (int o = 16; o; o >>= 1) accl += __shfl_xor_sync(0xffffffffu, accl, o);
        __shared__ float red2[8];
        if (lane == 0) red2[w] = accl;
        __syncthreads();
        if (tid == 0) {
            float t2 = 0.f;
            #pragma unroll
            for (int i = 0; i < 8; i++) t2 += red2[i];
            out[0] = t2 / (float)NB;
        }
    }
}

// ---------------- launch ----------------
extern "C" void kernel_launch(void* const* d_in, const int* in_sizes, int n_in,
                              void* d_out, int out_size) {
    const float* q      = (const float*)d_in[0];
    const float* doc    = (const float*)d_in[1];
    const int*   mask   = (const int*)d_in[2];
    const float* labels = (const float*)d_in[3];
    float* out = (float*)d_out;

    cudaFuncSetAttribute(maxsim_kernel,
                         cudaFuncAttributeMaxDynamicSharedMemorySize, SM_BYTES);

    maxsim_kernel<<<NB * NW, NTHR, SM_BYTES>>>(q, doc, mask, labels, out);
}